// round 1
// baseline (speedup 1.0000x reference)
#include <cuda_runtime.h>
#include <math.h>

#define NMAX 100000
#define EMAX 500000

// ---------------- scratch (static __device__, no allocation) ----------------
__device__ __align__(16) float g_XA[NMAX * 384];   // x @ V1[0:128,:]   (rows < bs used)
__device__ __align__(16) float g_XB[NMAX * 384];   // x @ V1[128:256,:] (all rows)
__device__ float g_signal[NMAX];
__device__ int   g_elist[EMAX];
__device__ int   g_ecount;
__device__ int   g_idx64;   // 1 if edge_index/y are int64-laid-out

// ---------------- init: reset counters/signal, sniff index dtype ------------
__global__ void init_kernel(int N, const int* __restrict__ ei_raw) {
    int i = blockIdx.x * blockDim.x + threadIdx.x;
    if (i == 0) {
        g_ecount = 0;
        int allz = 1;
        #pragma unroll
        for (int j = 1; j < 64; j += 2) {
            if (ei_raw[j] != 0) { allz = 0; break; }
        }
        g_idx64 = allz;
    }
    if (i < N) g_signal[i] = 0.0f;
}

// ---------------- compact edges with src < bs -------------------------------
__global__ void compact_kernel(const int* __restrict__ ei, int E,
                               const int* __restrict__ bs_ptr) {
    int e = blockIdx.x * blockDim.x + threadIdx.x;
    if (e >= E) return;
    int bs  = *bs_ptr;
    int i64 = g_idx64;
    int src = i64 ? ei[2 * e] : ei[e];
    if (src < bs) {
        int p = atomicAdd(&g_ecount, 1);
        g_elist[p] = e;
    }
}

// ---------------- XA / XB GEMM: out = x @ V1[koff:koff+128, :] --------------
// 64x64 tile, BK=32, 256 threads, 4x4 micro-tile.
__global__ __launch_bounds__(256) void xgemm_kernel(
    const float* __restrict__ A, const float* __restrict__ V1,
    int koff, int which, int M, const int* __restrict__ mlim_ptr)
{
    __shared__ __align__(16) float As[64 * 128];
    __shared__ __align__(16) float Bs[32 * 64];

    int Mlim = M;
    if (mlim_ptr) { int b = *mlim_ptr; Mlim = (b < M) ? b : M; }
    int row0 = blockIdx.x * 64;
    if (row0 >= Mlim) return;
    int ne = min(64, Mlim - row0);
    int t  = threadIdx.x;

    for (int i = t; i < 64 * 128; i += 256) {
        int r = i >> 7, c = i & 127;
        As[i] = (r < ne) ? A[(size_t)(row0 + r) * 128 + c] : 0.0f;
    }

    int ct = blockIdx.y;              // 0..5 (column tile of 64)
    int ty = t >> 4, tx = t & 15;
    float acc[4][4] = {};

    for (int kt = 0; kt < 4; ++kt) {
        __syncthreads();
        for (int i = t; i < 32 * 64; i += 256) {
            int kk = i >> 6, j = i & 63;
            Bs[i] = V1[(size_t)(koff + kt * 32 + kk) * 384 + ct * 64 + j];
        }
        __syncthreads();
        #pragma unroll
        for (int k = 0; k < 32; ++k) {
            float4 b4 = ((const float4*)Bs)[k * 16 + tx];
            float a0 = As[(ty * 4 + 0) * 128 + kt * 32 + k];
            float a1 = As[(ty * 4 + 1) * 128 + kt * 32 + k];
            float a2 = As[(ty * 4 + 2) * 128 + kt * 32 + k];
            float a3 = As[(ty * 4 + 3) * 128 + kt * 32 + k];
            acc[0][0] += a0 * b4.x; acc[0][1] += a0 * b4.y; acc[0][2] += a0 * b4.z; acc[0][3] += a0 * b4.w;
            acc[1][0] += a1 * b4.x; acc[1][1] += a1 * b4.y; acc[1][2] += a1 * b4.z; acc[1][3] += a1 * b4.w;
            acc[2][0] += a2 * b4.x; acc[2][1] += a2 * b4.y; acc[2][2] += a2 * b4.z; acc[2][3] += a2 * b4.w;
            acc[3][0] += a3 * b4.x; acc[3][1] += a3 * b4.y; acc[3][2] += a3 * b4.z; acc[3][3] += a3 * b4.w;
        }
    }

    float* outp = which ? g_XB : g_XA;
    #pragma unroll
    for (int i2 = 0; i2 < 4; ++i2) {
        int r = ty * 4 + i2;
        if (r < ne) {
            float4 v = make_float4(acc[i2][0], acc[i2][1], acc[i2][2], acc[i2][3]);
            *(float4*)(outp + (size_t)(row0 + r) * 384 + ct * 64 + tx * 4) = v;
        }
    }
}

// ---------------- node head: pred = relu(x@W1+b1)@W2 + b2 (rows < bs) -------
__global__ __launch_bounds__(256) void node_kernel(
    const float* __restrict__ x, const float* __restrict__ W1,
    const float* __restrict__ b1, const float* __restrict__ W2,
    const float* __restrict__ b2, float* __restrict__ out,
    int N, const int* __restrict__ bs_ptr)
{
    __shared__ __align__(16) float As[64 * 128];
    __shared__ __align__(16) float Bs[32 * 64];

    int bs = *bs_ptr; if (bs > N) bs = N;
    int row0 = blockIdx.x * 64;
    if (row0 >= bs) return;
    int ne = min(64, bs - row0);
    int t  = threadIdx.x;

    for (int i = t; i < 64 * 128; i += 256) {
        int r = i >> 7, c = i & 127;
        As[i] = (r < ne) ? x[(size_t)(row0 + r) * 128 + c] : 0.0f;
    }

    int ty = t >> 4, tx = t & 15;
    float o0[4] = {0, 0, 0, 0}, o1[4] = {0, 0, 0, 0};

    for (int ct = 0; ct < 2; ++ct) {
        float acc[4][4] = {};
        for (int kt = 0; kt < 4; ++kt) {
            __syncthreads();
            for (int i = t; i < 32 * 64; i += 256) {
                int kk = i >> 6, j = i & 63;
                Bs[i] = W1[(size_t)(kt * 32 + kk) * 128 + ct * 64 + j];
            }
            __syncthreads();
            #pragma unroll
            for (int k = 0; k < 32; ++k) {
                float4 b4 = ((const float4*)Bs)[k * 16 + tx];
                float a0 = As[(ty * 4 + 0) * 128 + kt * 32 + k];
                float a1 = As[(ty * 4 + 1) * 128 + kt * 32 + k];
                float a2 = As[(ty * 4 + 2) * 128 + kt * 32 + k];
                float a3 = As[(ty * 4 + 3) * 128 + kt * 32 + k];
                acc[0][0] += a0 * b4.x; acc[0][1] += a0 * b4.y; acc[0][2] += a0 * b4.z; acc[0][3] += a0 * b4.w;
                acc[1][0] += a1 * b4.x; acc[1][1] += a1 * b4.y; acc[1][2] += a1 * b4.z; acc[1][3] += a1 * b4.w;
                acc[2][0] += a2 * b4.x; acc[2][1] += a2 * b4.y; acc[2][2] += a2 * b4.z; acc[2][3] += a2 * b4.w;
                acc[3][0] += a3 * b4.x; acc[3][1] += a3 * b4.y; acc[3][2] += a3 * b4.z; acc[3][3] += a3 * b4.w;
            }
        }
        #pragma unroll
        for (int i2 = 0; i2 < 4; ++i2) {
            #pragma unroll
            for (int u = 0; u < 4; ++u) {
                int jg = ct * 64 + tx * 4 + u;
                float h = fmaxf(acc[i2][u] + b1[jg], 0.0f);
                o0[i2] += h * W2[jg * 2 + 0];
                o1[i2] += h * W2[jg * 2 + 1];
            }
        }
    }

    #pragma unroll
    for (int i2 = 0; i2 < 4; ++i2) {
        float v0 = o0[i2], v1 = o1[i2];
        #pragma unroll
        for (int off = 8; off >= 1; off >>= 1) {
            v0 += __shfl_xor_sync(0xffffffffu, v0, off, 16);
            v1 += __shfl_xor_sync(0xffffffffu, v1, off, 16);
        }
        if (tx == 0) {
            int r = ty * 4 + i2;
            if (r < ne) {
                out[(size_t)(row0 + r) * 2 + 0] = v0 + b2[0];
                out[(size_t)(row0 + r) * 2 + 1] = v1 + b2[1];
            }
        }
    }
}

// ---------------- fused edge kernel -----------------------------------------
// For each compacted edge: hidden = edge_attr@V1[256:,:] + XA[src] + XB[dst] + bv1
// score = relu(hidden) . V2 + bv2 ; sigmoid ; atomicMax into g_signal[src]
__global__ __launch_bounds__(256) void edge_kernel(
    const float* __restrict__ edge_attr, const float* __restrict__ V1,
    const float* __restrict__ bv1, const float* __restrict__ V2,
    const float* __restrict__ bv2, const int* __restrict__ ei, int E)
{
    __shared__ __align__(16) float As[64 * 128];
    __shared__ __align__(16) float Bs[32 * 64];
    __shared__ int s_src[64], s_dst[64];

    int base = blockIdx.x * 64;
    int cnt  = g_ecount;
    if (base >= cnt) return;
    int ne = min(64, cnt - base);
    int t  = threadIdx.x;
    int i64 = g_idx64;

    __shared__ int s_eid[64];
    if (t < 64) {
        int e = 0, ss = 0, dd = 0;
        if (t < ne) {
            e  = g_elist[base + t];
            ss = i64 ? ei[2 * e]       : ei[e];
            dd = i64 ? ei[2 * (E + e)] : ei[E + e];
        }
        s_eid[t] = e; s_src[t] = ss; s_dst[t] = dd;
    }
    __syncthreads();

    for (int i = t; i < 64 * 128; i += 256) {
        int r = i >> 7, c = i & 127;
        As[i] = (r < ne) ? edge_attr[(size_t)s_eid[r] * 128 + c] : 0.0f;
    }

    int ty = t >> 4, tx = t & 15;
    float esc[4] = {0, 0, 0, 0};   // per-lane partial score

    for (int ct = 0; ct < 6; ++ct) {
        float acc[4][4] = {};
        for (int kt = 0; kt < 4; ++kt) {
            __syncthreads();
            for (int i = t; i < 32 * 64; i += 256) {
                int kk = i >> 6, j = i & 63;
                Bs[i] = V1[(size_t)(256 + kt * 32 + kk) * 384 + ct * 64 + j];
            }
            __syncthreads();
            #pragma unroll
            for (int k = 0; k < 32; ++k) {
                float4 b4 = ((const float4*)Bs)[k * 16 + tx];
                float a0 = As[(ty * 4 + 0) * 128 + kt * 32 + k];
                float a1 = As[(ty * 4 + 1) * 128 + kt * 32 + k];
                float a2 = As[(ty * 4 + 2) * 128 + kt * 32 + k];
                float a3 = As[(ty * 4 + 3) * 128 + kt * 32 + k];
                acc[0][0] += a0 * b4.x; acc[0][1] += a0 * b4.y; acc[0][2] += a0 * b4.z; acc[0][3] += a0 * b4.w;
                acc[1][0] += a1 * b4.x; acc[1][1] += a1 * b4.y; acc[1][2] += a1 * b4.z; acc[1][3] += a1 * b4.w;
                acc[2][0] += a2 * b4.x; acc[2][1] += a2 * b4.y; acc[2][2] += a2 * b4.z; acc[2][3] += a2 * b4.w;
                acc[3][0] += a3 * b4.x; acc[3][1] += a3 * b4.y; acc[3][2] += a3 * b4.z; acc[3][3] += a3 * b4.w;
            }
        }
        int joff = ct * 64 + tx * 4;
        float4 vb1 = *(const float4*)(bv1 + joff);
        float4 vv2 = *(const float4*)(V2 + joff);
        #pragma unroll
        for (int i2 = 0; i2 < 4; ++i2) {
            int r = ty * 4 + i2;
            if (r < ne) {
                float4 va = *(const float4*)(g_XA + (size_t)s_src[r] * 384 + joff);
                float4 vb = *(const float4*)(g_XB + (size_t)s_dst[r] * 384 + joff);
                float h0 = fmaxf(acc[i2][0] + va.x + vb.x + vb1.x, 0.0f);
                float h1 = fmaxf(acc[i2][1] + va.y + vb.y + vb1.y, 0.0f);
                float h2 = fmaxf(acc[i2][2] + va.z + vb.z + vb1.z, 0.0f);
                float h3 = fmaxf(acc[i2][3] + va.w + vb.w + vb1.w, 0.0f);
                esc[i2] += h0 * vv2.x + h1 * vv2.y + h2 * vv2.z + h3 * vv2.w;
            }
        }
    }

    #pragma unroll
    for (int i2 = 0; i2 < 4; ++i2) {
        float v = esc[i2];
        #pragma unroll
        for (int off = 8; off >= 1; off >>= 1)
            v += __shfl_xor_sync(0xffffffffu, v, off, 16);
        if (tx == 0) {
            int r = ty * 4 + i2;
            if (r < ne) {
                float score = v + bv2[0];
                float sig = 1.0f / (1.0f + expf(-score));
                atomicMax((int*)&g_signal[s_src[r]], __float_as_int(sig));
            }
        }
    }
}

// ---------------- combine: add signal to col 1, emit labels ------------------
__global__ void combine_kernel(float* __restrict__ out, const float* __restrict__ ecw,
                               const int* __restrict__ y, const int* __restrict__ bs_ptr,
                               int out_size, int N)
{
    int r = blockIdx.x * blockDim.x + threadIdx.x;
    int bs = *bs_ptr; if (bs > N) bs = N;
    if (r >= bs) return;
    float w = *ecw;
    out[(size_t)r * 2 + 1] += w * g_signal[r];
    if (out_size >= 3 * bs) {
        int lab = g_idx64 ? y[2 * r] : y[r];
        out[(size_t)2 * bs + r] = (float)lab;
    }
}

// ---------------- launch -----------------------------------------------------
extern "C" void kernel_launch(void* const* d_in, const int* in_sizes, int n_in,
                              void* d_out, int out_size) {
    const float* x         = (const float*)d_in[0];
    const float* edge_attr = (const float*)d_in[1];
    const float* W1        = (const float*)d_in[2];
    const float* b1        = (const float*)d_in[3];
    const float* W2        = (const float*)d_in[4];
    const float* b2        = (const float*)d_in[5];
    const float* V1        = (const float*)d_in[6];
    const float* bv1       = (const float*)d_in[7];
    const float* V2        = (const float*)d_in[8];
    const float* bv2       = (const float*)d_in[9];
    const float* ecw       = (const float*)d_in[10];
    const int*   ei        = (const int*)d_in[11];
    const int*   y         = (const int*)d_in[12];
    const int*   bs_ptr    = (const int*)d_in[13];
    float* out = (float*)d_out;

    int N = in_sizes[0] / 128;
    int E = in_sizes[1] / 128;

    init_kernel<<<(N + 255) / 256, 256>>>(N, ei);
    compact_kernel<<<(E + 255) / 256, 256>>>(ei, E, bs_ptr);

    dim3 gx((N + 63) / 64, 6);
    xgemm_kernel<<<gx, 256>>>(x, V1, 0,   0, N, bs_ptr);   // XA (rows < bs)
    xgemm_kernel<<<gx, 256>>>(x, V1, 128, 1, N, nullptr);  // XB (all rows)

    node_kernel<<<(N + 63) / 64, 256>>>(x, W1, b1, W2, b2, out, N, bs_ptr);
    edge_kernel<<<(E + 63) / 64, 256>>>(edge_attr, V1, bv1, V2, bv2, ei, E);
    combine_kernel<<<(N + 255) / 256, 256>>>(out, ecw, y, bs_ptr, out_size, N);
}

// round 2
// speedup vs baseline: 1.2693x; 1.2693x over previous
#include <cuda_runtime.h>
#include <math.h>

#define NMAX 100000
#define EMAX 500000
#define ST 132          // padded smem stride (conflict-free frag reads)

// ---------------- scratch ----------------------------------------------------
__device__ __align__(16) float g_XAB[(size_t)NMAX * 768]; // [XA(384) | XB(384)]
__device__ __align__(16) float g_H[(size_t)NMAX * 128];   // relu(x@W1+b1), rows<bs
__device__ float g_signal[NMAX];
__device__ int   g_elist[EMAX];
__device__ int   g_ecount;
__device__ int   g_idx64;

// ---------------- mma helpers ------------------------------------------------
__device__ __forceinline__ unsigned f2tf(float f) {
    unsigned u; asm("cvt.rna.tf32.f32 %0, %1;" : "=r"(u) : "f"(f)); return u;
}
__device__ __forceinline__ void mma8(float* c, unsigned a0, unsigned a1,
                                     unsigned a2, unsigned a3,
                                     unsigned b0, unsigned b1) {
    asm volatile(
        "mma.sync.aligned.m16n8k8.row.col.f32.tf32.tf32.f32 "
        "{%0,%1,%2,%3},{%4,%5,%6,%7},{%8,%9},{%0,%1,%2,%3};"
        : "+f"(c[0]), "+f"(c[1]), "+f"(c[2]), "+f"(c[3])
        : "r"(a0), "r"(a1), "r"(a2), "r"(a3), "r"(b0), "r"(b1));
}

// ---------------- init / compact --------------------------------------------
__global__ void init_kernel(int N, const int* __restrict__ ei_raw) {
    int i = blockIdx.x * blockDim.x + threadIdx.x;
    if (i == 0) {
        g_ecount = 0;
        int allz = 1;
        #pragma unroll
        for (int j = 1; j < 64; j += 2)
            if (ei_raw[j] != 0) { allz = 0; break; }
        g_idx64 = allz;
    }
    if (i < N) g_signal[i] = 0.0f;
}

__global__ void compact_kernel(const int* __restrict__ ei, int E,
                               const int* __restrict__ bs_ptr) {
    int e = blockIdx.x * blockDim.x + threadIdx.x;
    if (e >= E) return;
    int bs  = *bs_ptr;
    int src = g_idx64 ? ei[2 * e] : ei[e];
    if (src < bs) {
        int p = atomicAdd(&g_ecount, 1);
        g_elist[p] = e;
    }
}

// ---------------- fused x-GEMM: x @ [V1a | V1b | W1] -------------------------
// grid.y = ct in 0..13:  ct<6: XA cols (limit bs); 6..11: XB cols (limit N);
//                        12,13: W1 hidden (limit bs, +b1, relu)
__global__ __launch_bounds__(256) void xgemm_mma(
    const float* __restrict__ x, const float* __restrict__ V1,
    const float* __restrict__ W1, const float* __restrict__ b1,
    int N, const int* __restrict__ bs_ptr)
{
    extern __shared__ unsigned dsm[];
    unsigned* As = dsm;             // [64][ST] tf32
    unsigned* Bs = dsm + 64 * ST;   // [n=64][k=128] transposed, stride ST

    int bs = *bs_ptr; if (bs > N) bs = N;
    int ct = blockIdx.y;
    int limit = (ct >= 6 && ct < 12) ? N : bs;
    int row0 = blockIdx.x * 64;
    if (row0 >= limit) return;
    int ne = min(64, limit - row0);
    int t = threadIdx.x;

    for (int i = t; i < 64 * 32; i += 256) {
        int r = i >> 5, c4 = i & 31;
        float4 v = (r < ne) ? *(const float4*)(x + (size_t)(row0 + r) * 128 + c4 * 4)
                            : make_float4(0.f, 0.f, 0.f, 0.f);
        unsigned* p = &As[r * ST + c4 * 4];
        p[0] = f2tf(v.x); p[1] = f2tf(v.y); p[2] = f2tf(v.z); p[3] = f2tf(v.w);
    }

    const float* Bsrc; int sb, koff, n0;
    if (ct < 6)       { Bsrc = V1; sb = 384; koff = 0;   n0 = ct * 64; }
    else if (ct < 12) { Bsrc = V1; sb = 384; koff = 128; n0 = (ct - 6) * 64; }
    else              { Bsrc = W1; sb = 128; koff = 0;   n0 = (ct - 12) * 64; }
    for (int i = t; i < 64 * 128; i += 256) {
        int k = i >> 6, n = i & 63;
        Bs[n * ST + k] = f2tf(Bsrc[(size_t)(koff + k) * sb + n0 + n]);
    }
    __syncthreads();

    int lane = t & 31, wid = t >> 5;
    int wm = wid >> 2, wn = wid & 3;        // 2 x 4 warp grid
    int g = lane >> 2, t4 = lane & 3;
    float C[2][2][4] = {};

    #pragma unroll
    for (int k0 = 0; k0 < 128; k0 += 8) {
        unsigned a[2][4], b[2][2];
        #pragma unroll
        for (int mi = 0; mi < 2; mi++) {
            int rb = wm * 32 + mi * 16;
            a[mi][0] = As[(rb + g)     * ST + k0 + t4];
            a[mi][1] = As[(rb + g + 8) * ST + k0 + t4];
            a[mi][2] = As[(rb + g)     * ST + k0 + t4 + 4];
            a[mi][3] = As[(rb + g + 8) * ST + k0 + t4 + 4];
        }
        #pragma unroll
        for (int ni = 0; ni < 2; ni++) {
            int nb = wn * 16 + ni * 8 + g;
            b[ni][0] = Bs[nb * ST + k0 + t4];
            b[ni][1] = Bs[nb * ST + k0 + t4 + 4];
        }
        #pragma unroll
        for (int mi = 0; mi < 2; mi++)
            #pragma unroll
            for (int ni = 0; ni < 2; ni++)
                mma8(C[mi][ni], a[mi][0], a[mi][1], a[mi][2], a[mi][3],
                     b[ni][0], b[ni][1]);
    }

    bool isH = (ct >= 12);
    #pragma unroll
    for (int mi = 0; mi < 2; mi++)
        #pragma unroll
        for (int ni = 0; ni < 2; ni++) {
            int ncl = wn * 16 + ni * 8 + 2 * t4;
            #pragma unroll
            for (int half = 0; half < 2; half++) {
                int r = wm * 32 + mi * 16 + g + half * 8;
                if (r < ne) {
                    float v0 = C[mi][ni][half * 2 + 0];
                    float v1 = C[mi][ni][half * 2 + 1];
                    size_t row = row0 + r;
                    if (isH) {
                        int jg = (ct - 12) * 64 + ncl;
                        float2 o;
                        o.x = fmaxf(v0 + b1[jg],     0.f);
                        o.y = fmaxf(v1 + b1[jg + 1], 0.f);
                        *(float2*)(g_H + row * 128 + jg) = o;
                    } else {
                        int jg = ct * 64 + ncl;  // 0..767
                        float2 o; o.x = v0; o.y = v1;
                        *(float2*)(g_XAB + row * 768 + jg) = o;
                    }
                }
            }
        }
}

// ---------------- edge kernel (mma + fused epilogue) -------------------------
__global__ __launch_bounds__(256) void edge_mma(
    const float* __restrict__ edge_attr, const float* __restrict__ V1,
    const float* __restrict__ bv1, const float* __restrict__ V2,
    const float* __restrict__ bv2, const int* __restrict__ ei, int E)
{
    extern __shared__ unsigned dsm[];
    unsigned* As   = dsm;                       // [64][ST] tf32 (persistent)
    unsigned* Bs   = dsm + 64 * ST;             // [n][k] per-ct
    float* s_xa    = (float*)(dsm + 2 * 64 * ST);   // [64][68]
    float* s_xb    = s_xa + 64 * 68;
    float* s_part  = s_xb + 64 * 68;            // [64][4] deterministic partials

    __shared__ int s_src[64], s_dst[64], s_eid[64];

    int cnt = g_ecount;
    int base = blockIdx.x * 64;
    if (base >= cnt) return;
    int ne = min(64, cnt - base);
    int t = threadIdx.x;
    int i64 = g_idx64;

    if (t < 64) {
        int e = 0, ss = 0, dd = 0;
        if (t < ne) {
            e  = g_elist[base + t];
            ss = i64 ? ei[2 * e]       : ei[e];
            dd = i64 ? ei[2 * (E + e)] : ei[E + e];
        }
        s_eid[t] = e; s_src[t] = ss; s_dst[t] = dd;
    }
    if (t < 256) { s_part[t] = 0.f; }
    __syncthreads();

    for (int i = t; i < 64 * 32; i += 256) {
        int r = i >> 5, c4 = i & 31;
        float4 v = (r < ne) ? *(const float4*)(edge_attr + (size_t)s_eid[r] * 128 + c4 * 4)
                            : make_float4(0.f, 0.f, 0.f, 0.f);
        unsigned* p = &As[r * ST + c4 * 4];
        p[0] = f2tf(v.x); p[1] = f2tf(v.y); p[2] = f2tf(v.z); p[3] = f2tf(v.w);
    }

    int lane = t & 31, wid = t >> 5;
    int wm = wid >> 2, wn = wid & 3;
    int g = lane >> 2, t4 = lane & 3;
    float psc[2][2] = {};    // per-(mi,half) row partial scores

    for (int ct = 0; ct < 6; ++ct) {
        __syncthreads();   // previous iter's consumers done (also orders As load)
        for (int i = t; i < 64 * 128; i += 256) {
            int k = i >> 6, n = i & 63;
            Bs[n * ST + k] = f2tf(V1[(size_t)(256 + k) * 384 + ct * 64 + n]);
        }
        for (int i = t; i < 64 * 16; i += 256) {
            int r = i >> 4, c4 = i & 15;
            float4 va, vb;
            if (r < ne) {
                va = *(const float4*)(g_XAB + (size_t)s_src[r] * 768 + ct * 64 + c4 * 4);
                vb = *(const float4*)(g_XAB + (size_t)s_dst[r] * 768 + 384 + ct * 64 + c4 * 4);
            } else { va = vb = make_float4(0.f, 0.f, 0.f, 0.f); }
            *(float4*)&s_xa[r * 68 + c4 * 4] = va;
            *(float4*)&s_xb[r * 68 + c4 * 4] = vb;
        }
        __syncthreads();

        float C[2][2][4] = {};
        #pragma unroll
        for (int k0 = 0; k0 < 128; k0 += 8) {
            unsigned a[2][4], b[2][2];
            #pragma unroll
            for (int mi = 0; mi < 2; mi++) {
                int rb = wm * 32 + mi * 16;
                a[mi][0] = As[(rb + g)     * ST + k0 + t4];
                a[mi][1] = As[(rb + g + 8) * ST + k0 + t4];
                a[mi][2] = As[(rb + g)     * ST + k0 + t4 + 4];
                a[mi][3] = As[(rb + g + 8) * ST + k0 + t4 + 4];
            }
            #pragma unroll
            for (int ni = 0; ni < 2; ni++) {
                int nb = wn * 16 + ni * 8 + g;
                b[ni][0] = Bs[nb * ST + k0 + t4];
                b[ni][1] = Bs[nb * ST + k0 + t4 + 4];
            }
            #pragma unroll
            for (int mi = 0; mi < 2; mi++)
                #pragma unroll
                for (int ni = 0; ni < 2; ni++)
                    mma8(C[mi][ni], a[mi][0], a[mi][1], a[mi][2], a[mi][3],
                         b[ni][0], b[ni][1]);
        }

        #pragma unroll
        for (int mi = 0; mi < 2; mi++)
            #pragma unroll
            for (int half = 0; half < 2; half++) {
                int r = wm * 32 + mi * 16 + g + half * 8;
                if (r < ne) {
                    #pragma unroll
                    for (int ni = 0; ni < 2; ni++) {
                        int ncl = wn * 16 + ni * 8 + 2 * t4;
                        int jg  = ct * 64 + ncl;
                        float2 bv = *(const float2*)(bv1 + jg);
                        float2 v2 = *(const float2*)(V2 + jg);
                        float h0 = fmaxf(C[mi][ni][half * 2 + 0] + s_xa[r * 68 + ncl]
                                         + s_xb[r * 68 + ncl] + bv.x, 0.f);
                        float h1 = fmaxf(C[mi][ni][half * 2 + 1] + s_xa[r * 68 + ncl + 1]
                                         + s_xb[r * 68 + ncl + 1] + bv.y, 0.f);
                        psc[mi][half] += h0 * v2.x + h1 * v2.y;
                    }
                }
            }
    }

    // deterministic reduction: shfl over t4, then fixed-order sum of 4 warp_n parts
    #pragma unroll
    for (int mi = 0; mi < 2; mi++)
        #pragma unroll
        for (int half = 0; half < 2; half++) {
            float v = psc[mi][half];
            v += __shfl_xor_sync(0xffffffffu, v, 1);
            v += __shfl_xor_sync(0xffffffffu, v, 2);
            int r = wm * 32 + mi * 16 + g + half * 8;
            if (t4 == 0 && r < ne) s_part[r * 4 + wn] = v;
        }
    __syncthreads();

    if (t < ne) {
        float score = ((s_part[t * 4 + 0] + s_part[t * 4 + 1])
                     + (s_part[t * 4 + 2] + s_part[t * 4 + 3])) + bv2[0];
        float sig = 1.0f / (1.0f + expf(-score));
        atomicMax((int*)&g_signal[s_src[t]], __float_as_int(sig));
    }
}

// ---------------- final: pred = H@W2 + b2 (+signal), labels ------------------
__global__ __launch_bounds__(256) void final_kernel(
    const float* __restrict__ W2, const float* __restrict__ b2,
    const float* __restrict__ ecw, const int* __restrict__ y,
    const int* __restrict__ bs_ptr, float* __restrict__ out,
    int out_size, int N)
{
    int bs = *bs_ptr; if (bs > N) bs = N;
    int row  = (blockIdx.x * blockDim.x + threadIdx.x) >> 5;
    int lane = threadIdx.x & 31;
    if (row >= bs) return;

    float4 hv  = *(const float4*)(g_H + (size_t)row * 128 + lane * 4);
    float4 w01 = *(const float4*)(W2 + lane * 8);
    float4 w23 = *(const float4*)(W2 + lane * 8 + 4);
    float d0 = hv.x * w01.x + hv.y * w01.z + hv.z * w23.x + hv.w * w23.z;
    float d1 = hv.x * w01.y + hv.y * w01.w + hv.z * w23.y + hv.w * w23.w;
    #pragma unroll
    for (int off = 16; off >= 1; off >>= 1) {
        d0 += __shfl_xor_sync(0xffffffffu, d0, off);
        d1 += __shfl_xor_sync(0xffffffffu, d1, off);
    }
    if (lane == 0) {
        out[(size_t)row * 2 + 0] = d0 + b2[0];
        out[(size_t)row * 2 + 1] = d1 + b2[1] + (*ecw) * g_signal[row];
        if (out_size >= 3 * bs) {
            int lab = g_idx64 ? y[2 * row] : y[row];
            out[(size_t)2 * bs + row] = (float)lab;
        }
    }
}

// ---------------- launch -----------------------------------------------------
extern "C" void kernel_launch(void* const* d_in, const int* in_sizes, int n_in,
                              void* d_out, int out_size) {
    const float* x         = (const float*)d_in[0];
    const float* edge_attr = (const float*)d_in[1];
    const float* W1        = (const float*)d_in[2];
    const float* b1        = (const float*)d_in[3];
    const float* W2        = (const float*)d_in[4];
    const float* b2        = (const float*)d_in[5];
    const float* V1        = (const float*)d_in[6];
    const float* bv1       = (const float*)d_in[7];
    const float* V2        = (const float*)d_in[8];
    const float* bv2       = (const float*)d_in[9];
    const float* ecw       = (const float*)d_in[10];
    const int*   ei        = (const int*)d_in[11];
    const int*   y         = (const int*)d_in[12];
    const int*   bs_ptr    = (const int*)d_in[13];
    float* out = (float*)d_out;

    int N = in_sizes[0] / 128;
    int E = in_sizes[1] / 128;

    int xg_smem = 2 * 64 * ST * 4;                           // 67.6 KB
    int eg_smem = (2 * 64 * ST + 2 * 64 * 68 + 256) * 4;     // ~103 KB
    cudaFuncSetAttribute(xgemm_mma, cudaFuncAttributeMaxDynamicSharedMemorySize, xg_smem);
    cudaFuncSetAttribute(edge_mma,  cudaFuncAttributeMaxDynamicSharedMemorySize, eg_smem);

    init_kernel<<<(N + 255) / 256, 256>>>(N, ei);
    compact_kernel<<<(E + 255) / 256, 256>>>(ei, E, bs_ptr);

    dim3 gx((N + 63) / 64, 14);
    xgemm_mma<<<gx, 256, xg_smem>>>(x, V1, W1, b1, N, bs_ptr);

    edge_mma<<<(E + 63) / 64, 256, eg_smem>>>(edge_attr, V1, bv1, V2, bv2, ei, E);

    final_kernel<<<(N * 32 + 255) / 256, 256>>>(W2, b2, ecw, y, bs_ptr, out, out_size, N);
}

// round 3
// speedup vs baseline: 1.8215x; 1.4350x over previous
#include <cuda_runtime.h>
#include <math.h>

#define NMAX 100000
#define EMAX 500000
#define AST 132      // As stride (words)
#define BST 72       // Bs k-major stride (words)

// ---------------- scratch ----------------------------------------------------
__device__ __align__(16) float g_XAB[(size_t)NMAX * 768]; // [XA(384) | XB(384)]
__device__ __align__(16) float g_H[(size_t)NMAX * 128];   // relu(x@W1+b1), rows<bs
__device__ float g_signal[NMAX];
__device__ int   g_elist[EMAX];
__device__ int   g_ecount;
__device__ int   g_idx64;

// ---------------- helpers -----------------------------------------------------
__device__ __forceinline__ unsigned f2tf(float f) {
    unsigned u; asm("cvt.rna.tf32.f32 %0, %1;" : "=r"(u) : "f"(f)); return u;
}
__device__ __forceinline__ void mma8(float* c, unsigned a0, unsigned a1,
                                     unsigned a2, unsigned a3,
                                     unsigned b0, unsigned b1) {
    asm volatile(
        "mma.sync.aligned.m16n8k8.row.col.f32.tf32.tf32.f32 "
        "{%0,%1,%2,%3},{%4,%5,%6,%7},{%8,%9},{%0,%1,%2,%3};"
        : "+f"(c[0]), "+f"(c[1]), "+f"(c[2]), "+f"(c[3])
        : "r"(a0), "r"(a1), "r"(a2), "r"(a3), "r"(b0), "r"(b1));
}
__device__ __forceinline__ void cp16(void* sdst, const void* gsrc) {
    unsigned s = (unsigned)__cvta_generic_to_shared(sdst);
    asm volatile("cp.async.cg.shared.global [%0], [%1], 16;\n" :: "r"(s), "l"(gsrc));
}
__device__ __forceinline__ void cp_commit() { asm volatile("cp.async.commit_group;\n" ::); }
__device__ __forceinline__ void cp_wait0()  { asm volatile("cp.async.wait_group 0;\n" ::); }
__device__ __forceinline__ void cp_wait1()  { asm volatile("cp.async.wait_group 1;\n" ::); }

// ---------------- init / compact ---------------------------------------------
__global__ void init_kernel(int N, const int* __restrict__ ei_raw) {
    int i = blockIdx.x * blockDim.x + threadIdx.x;
    if (i == 0) {
        g_ecount = 0;
        int allz = 1;
        #pragma unroll
        for (int j = 1; j < 64; j += 2)
            if (ei_raw[j] != 0) { allz = 0; break; }
        g_idx64 = allz;
    }
    if (i < N) g_signal[i] = 0.0f;
}

__global__ void compact_kernel(const int* __restrict__ ei, int E,
                               const int* __restrict__ bs_ptr) {
    int e = blockIdx.x * blockDim.x + threadIdx.x;
    if (e >= E) return;
    int bs  = *bs_ptr;
    int src = g_idx64 ? ei[2 * e] : ei[e];
    if (src < bs) {
        int p = atomicAdd(&g_ecount, 1);
        g_elist[p] = e;
    }
}

// ---------------- fused x-GEMM: x @ [V1a | V1b | W1], M=128 tiles ------------
// grid.y = ct in 0..13: ct<6 XA (limit bs); 6..11 XB (limit N); 12,13 W1+relu (bs)
__global__ __launch_bounds__(256) void xgemm_mma(
    const float* __restrict__ x, const float* __restrict__ V1,
    const float* __restrict__ W1, const float* __restrict__ b1,
    int N, const int* __restrict__ bs_ptr)
{
    extern __shared__ float fsm[];
    float* Asf = fsm;                 // [128][AST] raw fp32
    float* Bsf = fsm + 128 * AST;     // [128][BST] k-major raw fp32

    int bs = *bs_ptr; if (bs > N) bs = N;
    int ct = blockIdx.y;
    int limit = (ct >= 6 && ct < 12) ? N : bs;
    int row0 = blockIdx.x * 128;
    if (row0 >= limit) return;
    int ne = min(128, limit - row0);
    int t = threadIdx.x;

    for (int i = t; i < 128 * 32; i += 256) {
        int r = i >> 5, c4 = i & 31;
        int rs = (r < ne) ? (row0 + r) : row0;    // clamp: safe reads, garbage unused
        cp16(&Asf[r * AST + c4 * 4], x + (size_t)rs * 128 + c4 * 4);
    }
    const float* Bsrc; int sb, koff, n0;
    if (ct < 6)       { Bsrc = V1; sb = 384; koff = 0;   n0 = ct * 64; }
    else if (ct < 12) { Bsrc = V1; sb = 384; koff = 128; n0 = (ct - 6) * 64; }
    else              { Bsrc = W1; sb = 128; koff = 0;   n0 = (ct - 12) * 64; }
    for (int i = t; i < 2048; i += 256) {
        int k = i >> 4, n4 = i & 15;
        cp16(&Bsf[k * BST + n4 * 4], Bsrc + (size_t)(koff + k) * sb + n0 + n4 * 4);
    }
    cp_commit();
    cp_wait0();
    __syncthreads();

    int lane = t & 31, w = t >> 5;
    int wm = w >> 1, wn = w & 1;            // 4 x 2 warp grid, warp tile 32x32
    int g = lane >> 2, t4 = lane & 3;
    float C[2][4][4] = {};

    #pragma unroll
    for (int k0 = 0; k0 < 128; k0 += 8) {
        unsigned a[2][4], b[4][2];
        #pragma unroll
        for (int mi = 0; mi < 2; mi++) {
            int rb = wm * 32 + mi * 16;
            a[mi][0] = f2tf(Asf[(rb + g)     * AST + k0 + t4]);
            a[mi][1] = f2tf(Asf[(rb + g + 8) * AST + k0 + t4]);
            a[mi][2] = f2tf(Asf[(rb + g)     * AST + k0 + t4 + 4]);
            a[mi][3] = f2tf(Asf[(rb + g + 8) * AST + k0 + t4 + 4]);
        }
        #pragma unroll
        for (int ni = 0; ni < 4; ni++) {
            int nb = wn * 32 + ni * 8 + g;
            b[ni][0] = f2tf(Bsf[(k0 + t4)     * BST + nb]);
            b[ni][1] = f2tf(Bsf[(k0 + t4 + 4) * BST + nb]);
        }
        #pragma unroll
        for (int mi = 0; mi < 2; mi++)
            #pragma unroll
            for (int ni = 0; ni < 4; ni++)
                mma8(C[mi][ni], a[mi][0], a[mi][1], a[mi][2], a[mi][3],
                     b[ni][0], b[ni][1]);
    }

    bool isH = (ct >= 12);
    #pragma unroll
    for (int mi = 0; mi < 2; mi++)
        #pragma unroll
        for (int ni = 0; ni < 4; ni++) {
            int ncl = wn * 32 + ni * 8 + 2 * t4;
            #pragma unroll
            for (int half = 0; half < 2; half++) {
                int r = wm * 32 + mi * 16 + g + half * 8;
                if (r < ne) {
                    float v0 = C[mi][ni][half * 2 + 0];
                    float v1 = C[mi][ni][half * 2 + 1];
                    size_t row = row0 + r;
                    if (isH) {
                        int jg = (ct - 12) * 64 + ncl;
                        float2 o;
                        o.x = fmaxf(v0 + b1[jg],     0.f);
                        o.y = fmaxf(v1 + b1[jg + 1], 0.f);
                        *(float2*)(g_H + row * 128 + jg) = o;
                    } else {
                        int jg = ct * 64 + ncl;
                        float2 o; o.x = v0; o.y = v1;
                        *(float2*)(g_XAB + row * 768 + jg) = o;
                    }
                }
            }
        }
}

// ---------------- edge kernel: pipelined mma + register-gather epilogue ------
__global__ __launch_bounds__(256) void edge_mma(
    const float* __restrict__ edge_attr, const float* __restrict__ V1,
    const float* __restrict__ bv1, const float* __restrict__ V2,
    const float* __restrict__ bv2, const int* __restrict__ ei, int E)
{
    extern __shared__ unsigned dsm[];
    unsigned* As = dsm;                            // [64][AST] tf32 (persistent)
    float* Bs0 = (float*)(dsm + 64 * AST);         // [128][BST] double-buffered
    float* Bs1 = Bs0 + 128 * BST;

    __shared__ int s_src[64], s_dst[64], s_eid[64];
    __shared__ float s_part[64 * 4];

    int cnt = g_ecount;
    int base = blockIdx.x * 64;
    if (base >= cnt) return;
    int ne = min(64, cnt - base);
    int t = threadIdx.x;
    int i64 = g_idx64;

    if (t < 64) {
        int e = 0, ss = 0, dd = 0;
        if (t < ne) {
            e  = g_elist[base + t];
            ss = i64 ? ei[2 * e]       : ei[e];
            dd = i64 ? ei[2 * (E + e)] : ei[E + e];
        }
        s_eid[t] = e; s_src[t] = ss; s_dst[t] = dd;
    }
    s_part[t] = 0.f;
    __syncthreads();

    // kick off Bs[ct=0]
    for (int i = t; i < 2048; i += 256) {
        int k = i >> 4, n4 = i & 15;
        cp16(&Bs0[k * BST + n4 * 4], V1 + (size_t)(256 + k) * 384 + n4 * 4);
    }
    cp_commit();

    // As fill (edge_attr rows; clamped eid for r>=ne, garbage unused)
    for (int i = t; i < 64 * 32; i += 256) {
        int r = i >> 5, c4 = i & 31;
        float4 v = *(const float4*)(edge_attr + (size_t)s_eid[r] * 128 + c4 * 4);
        unsigned* p = &As[r * AST + c4 * 4];
        p[0] = f2tf(v.x); p[1] = f2tf(v.y); p[2] = f2tf(v.z); p[3] = f2tf(v.w);
    }

    int lane = t & 31, w = t >> 5;
    int wm = w >> 2, wn = w & 3;          // 2 x 4 warp grid, warp tile 32x16
    int g = lane >> 2, t4 = lane & 3;
    float psc[2][2] = {};

    for (int ct = 0; ct < 6; ++ct) {
        float* Bc = (ct & 1) ? Bs1 : Bs0;
        float* Bn = (ct & 1) ? Bs0 : Bs1;
        __syncthreads();   // all reads of Bn (prev iter) done; As visible at ct=0
        if (ct < 5) {
            for (int i = t; i < 2048; i += 256) {
                int k = i >> 4, n4 = i & 15;
                cp16(&Bn[k * BST + n4 * 4],
                     V1 + (size_t)(256 + k) * 384 + (ct + 1) * 64 + n4 * 4);
            }
        }
        cp_commit();       // possibly-empty group keeps accounting uniform
        cp_wait1();        // Bs[ct] complete (only newest group may be pending)
        __syncthreads();

        // register prefetch of XA/XB epilogue values (consumed after the k-loop)
        float2 pxa[2][2][2], pxb[2][2][2];    // [mi][half][ni]
        #pragma unroll
        for (int mi = 0; mi < 2; mi++)
            #pragma unroll
            for (int half = 0; half < 2; half++) {
                int r = wm * 32 + mi * 16 + g + half * 8;
                const float* pa = g_XAB + (size_t)s_src[r] * 768 + ct * 64;
                const float* pb = g_XAB + (size_t)s_dst[r] * 768 + 384 + ct * 64;
                #pragma unroll
                for (int ni = 0; ni < 2; ni++) {
                    int ncl = wn * 16 + ni * 8 + 2 * t4;
                    pxa[mi][half][ni] = *(const float2*)(pa + ncl);
                    pxb[mi][half][ni] = *(const float2*)(pb + ncl);
                }
            }

        float C[2][2][4] = {};
        #pragma unroll
        for (int k0 = 0; k0 < 128; k0 += 8) {
            unsigned a[2][4], b[2][2];
            #pragma unroll
            for (int mi = 0; mi < 2; mi++) {
                int rb = wm * 32 + mi * 16;
                a[mi][0] = As[(rb + g)     * AST + k0 + t4];
                a[mi][1] = As[(rb + g + 8) * AST + k0 + t4];
                a[mi][2] = As[(rb + g)     * AST + k0 + t4 + 4];
                a[mi][3] = As[(rb + g + 8) * AST + k0 + t4 + 4];
            }
            #pragma unroll
            for (int ni = 0; ni < 2; ni++) {
                int nb = wn * 16 + ni * 8 + g;
                b[ni][0] = f2tf(Bc[(k0 + t4)     * BST + nb]);
                b[ni][1] = f2tf(Bc[(k0 + t4 + 4) * BST + nb]);
            }
            #pragma unroll
            for (int mi = 0; mi < 2; mi++)
                #pragma unroll
                for (int ni = 0; ni < 2; ni++)
                    mma8(C[mi][ni], a[mi][0], a[mi][1], a[mi][2], a[mi][3],
                         b[ni][0], b[ni][1]);
        }

        #pragma unroll
        for (int mi = 0; mi < 2; mi++)
            #pragma unroll
            for (int half = 0; half < 2; half++) {
                int r = wm * 32 + mi * 16 + g + half * 8;
                if (r < ne) {
                    #pragma unroll
                    for (int ni = 0; ni < 2; ni++) {
                        int ncl = wn * 16 + ni * 8 + 2 * t4;
                        int jg  = ct * 64 + ncl;
                        float2 bv = *(const float2*)(bv1 + jg);
                        float2 v2 = *(const float2*)(V2 + jg);
                        float h0 = fmaxf(C[mi][ni][half * 2 + 0] + pxa[mi][half][ni].x
                                         + pxb[mi][half][ni].x + bv.x, 0.f);
                        float h1 = fmaxf(C[mi][ni][half * 2 + 1] + pxa[mi][half][ni].y
                                         + pxb[mi][half][ni].y + bv.y, 0.f);
                        psc[mi][half] += h0 * v2.x + h1 * v2.y;
                    }
                }
            }
    }

    // deterministic per-edge reduction
    #pragma unroll
    for (int mi = 0; mi < 2; mi++)
        #pragma unroll
        for (int half = 0; half < 2; half++) {
            float v = psc[mi][half];
            v += __shfl_xor_sync(0xffffffffu, v, 1);
            v += __shfl_xor_sync(0xffffffffu, v, 2);
            int r = wm * 32 + mi * 16 + g + half * 8;
            if (t4 == 0 && r < ne) s_part[r * 4 + wn] = v;
        }
    __syncthreads();

    if (t < ne) {
        float score = ((s_part[t * 4 + 0] + s_part[t * 4 + 1])
                     + (s_part[t * 4 + 2] + s_part[t * 4 + 3])) + bv2[0];
        float sig = 1.0f / (1.0f + expf(-score));
        atomicMax((int*)&g_signal[s_src[t]], __float_as_int(sig));
    }
}

// ---------------- final: pred = H@W2 + b2 (+signal), labels ------------------
__global__ __launch_bounds__(256) void final_kernel(
    const float* __restrict__ W2, const float* __restrict__ b2,
    const float* __restrict__ ecw, const int* __restrict__ y,
    const int* __restrict__ bs_ptr, float* __restrict__ out,
    int out_size, int N)
{
    int bs = *bs_ptr; if (bs > N) bs = N;
    int row  = (blockIdx.x * blockDim.x + threadIdx.x) >> 5;
    int lane = threadIdx.x & 31;
    if (row >= bs) return;

    float4 hv  = *(const float4*)(g_H + (size_t)row * 128 + lane * 4);
    float4 w01 = *(const float4*)(W2 + lane * 8);
    float4 w23 = *(const float4*)(W2 + lane * 8 + 4);
    float d0 = hv.x * w01.x + hv.y * w01.z + hv.z * w23.x + hv.w * w23.z;
    float d1 = hv.x * w01.y + hv.y * w01.w + hv.z * w23.y + hv.w * w23.w;
    #pragma unroll
    for (int off = 16; off >= 1; off >>= 1) {
        d0 += __shfl_xor_sync(0xffffffffu, d0, off);
        d1 += __shfl_xor_sync(0xffffffffu, d1, off);
    }
    if (lane == 0) {
        out[(size_t)row * 2 + 0] = d0 + b2[0];
        out[(size_t)row * 2 + 1] = d1 + b2[1] + (*ecw) * g_signal[row];
        if (out_size >= 3 * bs) {
            int lab = g_idx64 ? y[2 * row] : y[row];
            out[(size_t)2 * bs + row] = (float)lab;
        }
    }
}

// ---------------- launch -----------------------------------------------------
extern "C" void kernel_launch(void* const* d_in, const int* in_sizes, int n_in,
                              void* d_out, int out_size) {
    const float* x         = (const float*)d_in[0];
    const float* edge_attr = (const float*)d_in[1];
    const float* W1        = (const float*)d_in[2];
    const float* b1        = (const float*)d_in[3];
    const float* W2        = (const float*)d_in[4];
    const float* b2        = (const float*)d_in[5];
    const float* V1        = (const float*)d_in[6];
    const float* bv1       = (const float*)d_in[7];
    const float* V2        = (const float*)d_in[8];
    const float* bv2       = (const float*)d_in[9];
    const float* ecw       = (const float*)d_in[10];
    const int*   ei        = (const int*)d_in[11];
    const int*   y         = (const int*)d_in[12];
    const int*   bs_ptr    = (const int*)d_in[13];
    float* out = (float*)d_out;

    int N = in_sizes[0] / 128;
    int E = in_sizes[1] / 128;

    int xg_smem = (128 * AST + 128 * BST) * 4;          // ~104.4 KB
    int eg_smem = (64 * AST + 2 * 128 * BST) * 4;       // ~107.5 KB
    cudaFuncSetAttribute(xgemm_mma, cudaFuncAttributeMaxDynamicSharedMemorySize, xg_smem);
    cudaFuncSetAttribute(edge_mma,  cudaFuncAttributeMaxDynamicSharedMemorySize, eg_smem);

    init_kernel<<<(N + 255) / 256, 256>>>(N, ei);
    compact_kernel<<<(E + 255) / 256, 256>>>(ei, E, bs_ptr);

    dim3 gx((N + 127) / 128, 14);
    xgemm_mma<<<gx, 256, xg_smem>>>(x, V1, W1, b1, N, bs_ptr);

    edge_mma<<<(E + 63) / 64, 256, eg_smem>>>(edge_attr, V1, bv1, V2, bv2, ei, E);

    final_kernel<<<(N * 32 + 255) / 256, 256>>>(W2, b2, ecw, y, bs_ptr, out, out_size, N);
}